// round 5
// baseline (speedup 1.0000x reference)
#include <cuda_runtime.h>
#include <cuda_fp16.h>
#include <mma.h>
#include <cstdint>

using namespace nvcuda;

#define BB 4
#define SS 2048
#define DD 512
#define HH 8
#define HD 64
#define LDH 72   // half leading dim
#define LDF 68   // float leading dim

// q = x @ Wq, pre-split into fp16 hi/lo pairs (packed half2 per uint32)
__device__ uint32_t g_qh[(size_t)BB * SS * DD / 2];
__device__ uint32_t g_ql[(size_t)BB * SS * DD / 2];

__device__ __forceinline__ float f16hi(float v) {
    return __half2float(__float2half_rn(v));
}
__device__ __forceinline__ uint32_t packh2(float a, float b) {
    __half2 h = __floats2half2_rn(a, b);
    return *(uint32_t*)&h;
}

// ---------------------------------------------------------------------------
// Kernel 1: q = x @ Wq  via fp16 wmma, 3-term split (hi,lo).
// ---------------------------------------------------------------------------
__global__ __launch_bounds__(256) void qproj_kernel(const float* __restrict__ x,
                                                    const float* __restrict__ w) {
    __shared__ __align__(16) __half Ah[64 * LDH];
    __shared__ __align__(16) __half Al[64 * LDH];
    __shared__ __align__(16) __half Bh[64 * LDH];
    __shared__ __align__(16) __half Bl[64 * LDH];

    const int tid  = threadIdx.x;
    const int warp = tid >> 5;
    const int tr   = warp >> 1;
    const int tcb  = (warp & 1) * 2;
    const int bm   = blockIdx.x;
    const int bn   = blockIdx.y;

    wmma::fragment<wmma::accumulator, 16, 16, 16, float> c[2];
    wmma::fill_fragment(c[0], 0.f);
    wmma::fill_fragment(c[1], 0.f);

    const float* xbase = x + (size_t)bm * 64 * DD;

    for (int k0 = 0; k0 < DD; k0 += 64) {
#pragma unroll
        for (int i = tid; i < 1024; i += 256) {
            int rr = i >> 4, c4 = (i & 15) << 2;
            float4 a = *(const float4*)(xbase + (size_t)rr * DD + k0 + c4);
            float4 b = *(const float4*)(w + (size_t)(k0 + rr) * DD + bn * 64 + c4);
            uint32_t* Ahp = (uint32_t*)(Ah + rr * LDH + c4);
            uint32_t* Alp = (uint32_t*)(Al + rr * LDH + c4);
            uint32_t* Bhp = (uint32_t*)(Bh + rr * LDH + c4);
            uint32_t* Blp = (uint32_t*)(Bl + rr * LDH + c4);
            Ahp[0] = packh2(a.x, a.y);
            Ahp[1] = packh2(a.z, a.w);
            Alp[0] = packh2(a.x - f16hi(a.x), a.y - f16hi(a.y));
            Alp[1] = packh2(a.z - f16hi(a.z), a.w - f16hi(a.w));
            Bhp[0] = packh2(b.x, b.y);
            Bhp[1] = packh2(b.z, b.w);
            Blp[0] = packh2(b.x - f16hi(b.x), b.y - f16hi(b.y));
            Blp[1] = packh2(b.z - f16hi(b.z), b.w - f16hi(b.w));
        }
        __syncthreads();

#pragma unroll
        for (int kk = 0; kk < 64; kk += 16) {
            wmma::fragment<wmma::matrix_a, 16, 16, 16, __half, wmma::row_major> a_h, a_l;
            wmma::load_matrix_sync(a_h, Ah + tr * 16 * LDH + kk, LDH);
            wmma::load_matrix_sync(a_l, Al + tr * 16 * LDH + kk, LDH);
#pragma unroll
            for (int t = 0; t < 2; t++) {
                wmma::fragment<wmma::matrix_b, 16, 16, 16, __half, wmma::row_major> b_h, b_l;
                wmma::load_matrix_sync(b_h, Bh + kk * LDH + (tcb + t) * 16, LDH);
                wmma::load_matrix_sync(b_l, Bl + kk * LDH + (tcb + t) * 16, LDH);
                wmma::mma_sync(c[t], a_h, b_h, c[t]);
                wmma::mma_sync(c[t], a_l, b_h, c[t]);
                wmma::mma_sync(c[t], a_h, b_l, c[t]);
            }
        }
        __syncthreads();
    }

    float* Cs = (float*)Ah;
#pragma unroll
    for (int t = 0; t < 2; t++)
        wmma::store_matrix_sync(Cs + tr * 16 * LDF + (tcb + t) * 16, c[t], LDF, wmma::mem_row_major);
    __syncthreads();

#pragma unroll
    for (int i = tid; i < 2048; i += 256) {
        int rr = i >> 5, wv = i & 31;
        float c0 = Cs[rr * LDF + 2 * wv];
        float c1 = Cs[rr * LDF + 2 * wv + 1];
        size_t word = (size_t)(bm * 64 + rr) * (DD / 2) + bn * 32 + wv;
        g_qh[word] = packh2(c0, c1);
        g_ql[word] = packh2(c0 - f16hi(c0), c1 - f16hi(c1));
    }
}

// ---------------------------------------------------------------------------
// Kernel 2: flash attention, CTA tile 128(q) x 64(k), 8 warps 4x2, 32x32/warp.
// exp applied directly on accumulator fragments (runtime layout discovery),
// P scattered to SMEM as fp16 hi/lo, row-sums in registers (atomic at end).
// Static per-row shift m_i = 0.125*|q_i|^2.
// ---------------------------------------------------------------------------
#define OQH  0u
#define OQL  18432u
#define OKH  36864u
#define OKL  46080u
#define OPH  55296u      // also fp32 epilogue buffer (needs 34816 <= 36864)
#define OPL  73728u
#define OIDX 92160u      // 16x16 fp32 index matrix
#define OMR  93184u      // mrow: 128 f32
#define OLR  93696u      // lrow: 128 f32
#define ATTN_SMEM_BYTES 94208

__global__ __launch_bounds__(256) void attn_kernel(float* __restrict__ out) {
    extern __shared__ __align__(16) char dsm[];
    __half* Qh = (__half*)(dsm + OQH);
    __half* Ql = (__half*)(dsm + OQL);
    __half* Kh = (__half*)(dsm + OKH);
    __half* Kl = (__half*)(dsm + OKL);
    __half* Ph = (__half*)(dsm + OPH);
    __half* Pl = (__half*)(dsm + OPL);
    float*  Idx  = (float*)(dsm + OIDX);
    float*  mrow = (float*)(dsm + OMR);
    float*  lrow = (float*)(dsm + OLR);

    const int tid    = threadIdx.x;
    const int warp   = tid >> 5;
    const int warp_r = warp >> 1;        // 0..3
    const int warp_c = warp & 1;         // 0..1
    const int qblk = blockIdx.x;         // 0..15
    const int bh   = blockIdx.y;         // 0..31
    const int b = bh >> 3, h = bh & 7;

    const uint4* gqh = (const uint4*)g_qh;
    const uint4* gql = (const uint4*)g_ql;

    // ---- load Q tile (128 x 64), index matrix, init lrow ----
#pragma unroll
    for (int i = tid; i < 1024; i += 256) {
        int r = i >> 3, c = i & 7;
        size_t idx = (size_t)(b * SS + qblk * 128 + r) * 64 + h * 8 + c;
        *(uint4*)(Qh + r * LDH + c * 8) = gqh[idx];
        *(uint4*)(Ql + r * LDH + c * 8) = gql[idx];
    }
    Idx[tid] = (float)tid;   // Idx[r][c] = r*16+c, stride 16
    if (tid < 128) lrow[tid] = 0.f;
    __syncthreads();

    // per-row static shift m_i = 0.125 * |q_i|^2
    if (tid < 128) {
        float n2 = 0.f;
#pragma unroll
        for (int c = 0; c < 64; c++) {
            float v = __half2float(Qh[tid * LDH + c]) + __half2float(Ql[tid * LDH + c]);
            n2 = fmaf(v, v, n2);
        }
        mrow[tid] = 0.125f * n2;
    }
    __syncthreads();

    // ---- runtime fragment layout discovery ----
    wmma::fragment<wmma::accumulator, 16, 16, 16, float> idxf;
    wmma::load_matrix_sync(idxf, Idx, 16, wmma::mem_row_major);
    int er[8], ec[8];
    float mreg[2][8];
#pragma unroll
    for (int i = 0; i < 8; i++) {
        int e = (int)idxf.x[i];
        er[i] = e >> 4;
        ec[i] = e & 15;
        mreg[0][i] = mrow[warp_r * 32 + er[i]];
        mreg[1][i] = mrow[warp_r * 32 + 16 + er[i]];
    }

    float lacc[2][8];
#pragma unroll
    for (int sr = 0; sr < 2; sr++)
#pragma unroll
        for (int i = 0; i < 8; i++) lacc[sr][i] = 0.f;

    wmma::fragment<wmma::accumulator, 16, 16, 16, float> o[2][2];
#pragma unroll
    for (int sr = 0; sr < 2; sr++)
#pragma unroll
        for (int sc = 0; sc < 2; sc++) wmma::fill_fragment(o[sr][sc], 0.f);

    for (int j = 0; j < SS / 64; j++) {
        __syncthreads();  // prev PV done reading Kh/Kl/Ph/Pl

        // ---- load K/V tile (64 x 64) ----
#pragma unroll
        for (int i = tid; i < 512; i += 256) {
            int r = i >> 3, c = i & 7;
            size_t idx = (size_t)(b * SS + j * 64 + r) * 64 + h * 8 + c;
            *(uint4*)(Kh + r * LDH + c * 8) = gqh[idx];
            *(uint4*)(Kl + r * LDH + c * 8) = gql[idx];
        }
        __syncthreads();

        // ---- S = Q K^T (3-term fp16), warp tile 32x32 ----
        wmma::fragment<wmma::accumulator, 16, 16, 16, float> s[2][2];
#pragma unroll
        for (int sr = 0; sr < 2; sr++)
#pragma unroll
            for (int sc = 0; sc < 2; sc++) wmma::fill_fragment(s[sr][sc], 0.f);

#pragma unroll
        for (int kk = 0; kk < 64; kk += 16) {
            wmma::fragment<wmma::matrix_a, 16, 16, 16, __half, wmma::row_major> a_h[2], a_l[2];
#pragma unroll
            for (int sr = 0; sr < 2; sr++) {
                wmma::load_matrix_sync(a_h[sr], Qh + (warp_r * 32 + sr * 16) * LDH + kk, LDH);
                wmma::load_matrix_sync(a_l[sr], Ql + (warp_r * 32 + sr * 16) * LDH + kk, LDH);
            }
#pragma unroll
            for (int sc = 0; sc < 2; sc++) {
                wmma::fragment<wmma::matrix_b, 16, 16, 16, __half, wmma::col_major> b_h, b_l;
                wmma::load_matrix_sync(b_h, Kh + (warp_c * 32 + sc * 16) * LDH + kk, LDH);
                wmma::load_matrix_sync(b_l, Kl + (warp_c * 32 + sc * 16) * LDH + kk, LDH);
#pragma unroll
                for (int sr = 0; sr < 2; sr++) {
                    wmma::mma_sync(s[sr][sc], a_h[sr], b_h, s[sr][sc]);
                    wmma::mma_sync(s[sr][sc], a_l[sr], b_h, s[sr][sc]);
                    wmma::mma_sync(s[sr][sc], a_h[sr], b_l, s[sr][sc]);
                }
            }
        }

        // ---- exp in fragments, scatter P hi/lo to SMEM, row-sum in regs ----
#pragma unroll
        for (int sr = 0; sr < 2; sr++) {
#pragma unroll
            for (int i = 0; i < 8; i++) {
                const int row = warp_r * 32 + sr * 16 + er[i];
                const float m = mreg[sr][i];
#pragma unroll
                for (int sc = 0; sc < 2; sc++) {
                    float p = __expf(fmaf(s[sr][sc].x[i], 0.125f, -m));
                    lacc[sr][i] += p;
                    const int col = warp_c * 32 + sc * 16 + ec[i];
                    float ph = f16hi(p);
                    Ph[row * LDH + col] = __float2half_rn(p);
                    Pl[row * LDH + col] = __float2half_rn(p - ph);
                }
            }
        }
        __syncthreads();

        // ---- O += P V (3-term fp16), V = K tile row-major ----
#pragma unroll
        for (int kk = 0; kk < 64; kk += 16) {
            wmma::fragment<wmma::matrix_a, 16, 16, 16, __half, wmma::row_major> p_h[2], p_l[2];
#pragma unroll
            for (int sr = 0; sr < 2; sr++) {
                wmma::load_matrix_sync(p_h[sr], Ph + (warp_r * 32 + sr * 16) * LDH + kk, LDH);
                wmma::load_matrix_sync(p_l[sr], Pl + (warp_r * 32 + sr * 16) * LDH + kk, LDH);
            }
#pragma unroll
            for (int sc = 0; sc < 2; sc++) {
                wmma::fragment<wmma::matrix_b, 16, 16, 16, __half, wmma::row_major> v_h, v_l;
                wmma::load_matrix_sync(v_h, Kh + kk * LDH + (warp_c * 32 + sc * 16), LDH);
                wmma::load_matrix_sync(v_l, Kl + kk * LDH + (warp_c * 32 + sc * 16), LDH);
#pragma unroll
                for (int sr = 0; sr < 2; sr++) {
                    wmma::mma_sync(o[sr][sc], p_h[sr], v_h, o[sr][sc]);
                    wmma::mma_sync(o[sr][sc], p_l[sr], v_h, o[sr][sc]);
                    wmma::mma_sync(o[sr][sc], p_h[sr], v_l, o[sr][sc]);
                }
            }
        }
    }

    __syncthreads();  // all PV reads of Ph done before fp32 reuse

    // ---- commit row sums (warp_c 0/1 both add; atomics serialize) ----
#pragma unroll
    for (int sr = 0; sr < 2; sr++)
#pragma unroll
        for (int i = 0; i < 8; i++)
            atomicAdd(&lrow[warp_r * 32 + sr * 16 + er[i]], lacc[sr][i]);

    // ---- store O fragments to fp32 buffer (reuse Ph/Pl space) ----
    float* Pf = (float*)(dsm + OPH);  // 128 x LDF
#pragma unroll
    for (int sr = 0; sr < 2; sr++)
#pragma unroll
        for (int sc = 0; sc < 2; sc++)
            wmma::store_matrix_sync(Pf + (warp_r * 32 + sr * 16) * LDF + warp_c * 32 + sc * 16,
                                    o[sr][sc], LDF, wmma::mem_row_major);
    __syncthreads();

    // ---- epilogue: out = O / l ----
    float* obase = out + (size_t)b * SS * DD + (size_t)h * HD;
#pragma unroll
    for (int i = tid; i < 2048; i += 256) {
        int r = i >> 4, c4 = (i & 15) << 2;
        float inv = 1.f / lrow[r];
        float4 v = *(float4*)(Pf + r * LDF + c4);
        v.x *= inv; v.y *= inv; v.z *= inv; v.w *= inv;
        *(float4*)(obase + (size_t)(qblk * 128 + r) * DD + c4) = v;
    }
}

extern "C" void kernel_launch(void* const* d_in, const int* in_sizes, int n_in,
                              void* d_out, int out_size) {
    const float* x  = (const float*)d_in[0];
    const float* Wq = (const float*)d_in[1];
    float* out = (float*)d_out;

    cudaFuncSetAttribute(attn_kernel, cudaFuncAttributeMaxDynamicSharedMemorySize, ATTN_SMEM_BYTES);

    qproj_kernel<<<dim3(128, 8), 256>>>(x, Wq);
    attn_kernel<<<dim3(SS / 128, BB * HH), 256, ATTN_SMEM_BYTES>>>(out);
}